// round 1
// baseline (speedup 1.0000x reference)
#include <cuda_runtime.h>
#include <math.h>

// ---------------- problem constants ----------------
#define BATCH    512
#define NNODE    256
#define MROWS    (BATCH*NNODE)   // 131072
#define NODE_D   256
#define FEAT_IN  512
#define GLOB_D   64
#define IN_DIM   576             // FEAT_IN + GLOB_D
#define FEAT_HID 1024
#define ATTN_HID 256
#define FEAT_OUT 256
#define NHEADS   4
#define LN_EPS   1e-5f

// ---------------- scratch (static device globals; no allocation) ----------------
__device__ float g_inp[(size_t)MROWS * IN_DIM];      // LN output + ctx, 302 MB
__device__ float g_h1[(size_t)MROWS * FEAT_HID];     // feature hidden, 537 MB
__device__ float g_a1[(size_t)MROWS * ATTN_HID];     // attn hidden, 134 MB
__device__ float g_feats[(size_t)MROWS * FEAT_OUT];  // feature out, 134 MB
__device__ float g_scores[(size_t)MROWS * NHEADS];   // 2 MB
__device__ float g_w[(size_t)MROWS * NHEADS];        // softmax weights, 2 MB

// ---------------- stage 1: LayerNorm(concat) + ctx concat ----------------
// one block (128 threads) per row; each thread owns 4 contiguous elements
__global__ void prep_kernel(const float* __restrict__ nodes,
                            const float* __restrict__ pe,
                            const float* __restrict__ globs,
                            const float* __restrict__ ln_g,
                            const float* __restrict__ ln_b) {
    int row = blockIdx.x;
    int t = threadIdx.x;        // 0..127
    int b = row >> 8;

    float4 v;
    if (t < 64) v = ((const float4*)(nodes + (size_t)row * NODE_D))[t];
    else        v = ((const float4*)(pe    + (size_t)row * NODE_D))[t - 64];

    float s  = v.x + v.y + v.z + v.w;
    float ss = v.x * v.x + v.y * v.y + v.z * v.z + v.w * v.w;
    #pragma unroll
    for (int o = 16; o; o >>= 1) {
        s  += __shfl_xor_sync(0xFFFFFFFFu, s, o);
        ss += __shfl_xor_sync(0xFFFFFFFFu, ss, o);
    }
    __shared__ float sh_s[4], sh_ss[4];
    if ((t & 31) == 0) { sh_s[t >> 5] = s; sh_ss[t >> 5] = ss; }
    __syncthreads();
    float mean = (sh_s[0] + sh_s[1] + sh_s[2] + sh_s[3]) * (1.f / 512.f);
    float m2   = (sh_ss[0] + sh_ss[1] + sh_ss[2] + sh_ss[3]) * (1.f / 512.f);
    float rstd = rsqrtf(m2 - mean * mean + LN_EPS);

    float4 g  = ((const float4*)ln_g)[t];
    float4 bt = ((const float4*)ln_b)[t];
    float4 o;
    o.x = (v.x - mean) * rstd * g.x + bt.x;
    o.y = (v.y - mean) * rstd * g.y + bt.y;
    o.z = (v.z - mean) * rstd * g.z + bt.z;
    o.w = (v.w - mean) * rstd * g.w + bt.w;
    ((float4*)(g_inp + (size_t)row * IN_DIM))[t] = o;
    if (t < 16) {
        ((float4*)(g_inp + (size_t)row * IN_DIM + FEAT_IN))[t] =
            ((const float4*)(globs + (size_t)b * GLOB_D))[t];
    }
}

// ---------------- stage 2: tiled SGEMM, C = act(A @ W + bias) ----------------
// A: [M,K] row-major, W: [K,Nc] row-major. BM=BN=128, BK=8, 256 threads, 8x8/thread.
template <bool SILU>
__global__ void __launch_bounds__(256, 2)
sgemm_kernel(const float* __restrict__ A, const float* __restrict__ W,
             const float* __restrict__ bias, float* __restrict__ C,
             int K, int Nc) {
    __shared__ float As[8][128];
    __shared__ float Ws[8][128];
    int t = threadIdx.x;
    int brow = blockIdx.y * 128;
    int bcol = blockIdx.x * 128;
    int tx = t & 15, ty = t >> 4;

    float acc[8][8];
    #pragma unroll
    for (int i = 0; i < 8; i++)
        #pragma unroll
        for (int j = 0; j < 8; j++) acc[i][j] = 0.f;

    int ar = t >> 1;              // 0..127
    int ac = (t & 1) * 4;         // 0 or 4
    int wr = t >> 5;              // 0..7
    int wc = (t & 31) * 4;        // 0..124
    const float* Aptr = A + (size_t)(brow + ar) * K + ac;
    const float* Wptr = W + (size_t)wr * Nc + bcol + wc;

    for (int k0 = 0; k0 < K; k0 += 8) {
        float4 av = *(const float4*)(Aptr + k0);
        float4 wv = *(const float4*)(Wptr + (size_t)k0 * Nc);
        __syncthreads();
        As[ac + 0][ar] = av.x;
        As[ac + 1][ar] = av.y;
        As[ac + 2][ar] = av.z;
        As[ac + 3][ar] = av.w;
        *(float4*)&Ws[wr][wc] = wv;
        __syncthreads();
        #pragma unroll
        for (int k = 0; k < 8; k++) {
            float a[8], bb[8];
            *(float4*)&a[0]  = *(const float4*)&As[k][ty * 4];
            *(float4*)&a[4]  = *(const float4*)&As[k][64 + ty * 4];
            *(float4*)&bb[0] = *(const float4*)&Ws[k][tx * 4];
            *(float4*)&bb[4] = *(const float4*)&Ws[k][64 + tx * 4];
            #pragma unroll
            for (int i = 0; i < 8; i++)
                #pragma unroll
                for (int j = 0; j < 8; j++)
                    acc[i][j] += a[i] * bb[j];
        }
    }

    #pragma unroll
    for (int ri = 0; ri < 2; ri++) {
        #pragma unroll
        for (int i = 0; i < 4; i++) {
            int row = brow + ri * 64 + ty * 4 + i;
            #pragma unroll
            for (int cj = 0; cj < 2; cj++) {
                int col = bcol + cj * 64 + tx * 4;
                float4 v;
                v.x = acc[ri * 4 + i][cj * 4 + 0] + bias[col + 0];
                v.y = acc[ri * 4 + i][cj * 4 + 1] + bias[col + 1];
                v.z = acc[ri * 4 + i][cj * 4 + 2] + bias[col + 2];
                v.w = acc[ri * 4 + i][cj * 4 + 3] + bias[col + 3];
                if (SILU) {
                    v.x = v.x / (1.f + __expf(-v.x));
                    v.y = v.y / (1.f + __expf(-v.y));
                    v.z = v.z / (1.f + __expf(-v.z));
                    v.w = v.w / (1.f + __expf(-v.w));
                }
                *(float4*)&C[(size_t)row * Nc + col] = v;
            }
        }
    }
}

// ---------------- stage 3: scores = A1 @ aw2 + ab2  (K=256, 4 outputs/row) ----------------
__global__ void scores_kernel(const float* __restrict__ A1,
                              const float* __restrict__ aw2,
                              const float* __restrict__ ab2) {
    int warp = (blockIdx.x * blockDim.x + threadIdx.x) >> 5;
    int lane = threadIdx.x & 31;
    if (warp >= MROWS) return;
    const float* a = A1 + (size_t)warp * ATTN_HID;
    float acc0 = 0.f, acc1 = 0.f, acc2 = 0.f, acc3 = 0.f;
    #pragma unroll
    for (int c = 0; c < 8; c++) {
        int k = c * 32 + lane;
        float av = a[k];
        float4 w = ((const float4*)aw2)[k];
        acc0 += av * w.x; acc1 += av * w.y; acc2 += av * w.z; acc3 += av * w.w;
    }
    #pragma unroll
    for (int o = 16; o; o >>= 1) {
        acc0 += __shfl_xor_sync(0xFFFFFFFFu, acc0, o);
        acc1 += __shfl_xor_sync(0xFFFFFFFFu, acc1, o);
        acc2 += __shfl_xor_sync(0xFFFFFFFFu, acc2, o);
        acc3 += __shfl_xor_sync(0xFFFFFFFFu, acc3, o);
    }
    if (lane == 0) {
        float4 r;
        r.x = acc0 + ab2[0]; r.y = acc1 + ab2[1];
        r.z = acc2 + ab2[2]; r.w = acc3 + ab2[3];
        ((float4*)g_scores)[warp] = r;
    }
}

// ---------------- stage 4: masked softmax over nodes, per (b, head) ----------------
// one block (256 threads) per graph; each thread owns one node
__global__ void softmax_kernel(const int* __restrict__ mask) {
    int b = blockIdx.x;
    int t = threadIdx.x;      // node index
    int valid = mask[b * NNODE + t];
    __shared__ float sred[8];
    #pragma unroll
    for (int h = 0; h < NHEADS; h++) {
        float s = valid ? g_scores[((size_t)b * NNODE + t) * NHEADS + h] * 0.0625f
                        : -INFINITY;
        // block max
        float m = s;
        #pragma unroll
        for (int o = 16; o; o >>= 1) m = fmaxf(m, __shfl_xor_sync(0xFFFFFFFFu, m, o));
        if ((t & 31) == 0) sred[t >> 5] = m;
        __syncthreads();
        m = fmaxf(fmaxf(fmaxf(sred[0], sred[1]), fmaxf(sred[2], sred[3])),
                  fmaxf(fmaxf(sred[4], sred[5]), fmaxf(sred[6], sred[7])));
        __syncthreads();
        float e = expf(s - m);            // exp(-inf - finite) = 0 for masked
        float sum = e;
        #pragma unroll
        for (int o = 16; o; o >>= 1) sum += __shfl_xor_sync(0xFFFFFFFFu, sum, o);
        if ((t & 31) == 0) sred[t >> 5] = sum;
        __syncthreads();
        sum = sred[0] + sred[1] + sred[2] + sred[3] +
              sred[4] + sred[5] + sred[6] + sred[7];
        g_w[((size_t)b * NNODE + t) * NHEADS + h] = e / sum;
        __syncthreads();
    }
}

// ---------------- stage 5: residual add + masked feats + attention pooling ----------------
// one block (256 threads = channels) per graph
__global__ void finalize_kernel(const float* __restrict__ nodes,
                                const int* __restrict__ mask,
                                float* __restrict__ out) {
    int b = blockIdx.x;
    int c = threadIdx.x;                  // channel 0..255
    int h = c >> 6;                       // head for this channel
    const float* nb = nodes   + (size_t)b * NNODE * FEAT_OUT;
    const float* fb = g_feats + (size_t)b * NNODE * FEAT_OUT;
    float*       ob = out     + (size_t)b * NNODE * FEAT_OUT;
    float acc = 0.f;
    for (int n = 0; n < NNODE; n++) {
        float f = mask[b * NNODE + n] ? fb[n * FEAT_OUT + c] : 0.f;
        float v = nb[n * FEAT_OUT + c] + f;
        ob[n * FEAT_OUT + c] = v;
        acc += v * g_w[((size_t)b * NNODE + n) * NHEADS + h];
    }
    out[(size_t)MROWS * FEAT_OUT + (size_t)b * FEAT_OUT + c] = acc;
}

// ---------------- launch ----------------
extern "C" void kernel_launch(void* const* d_in, const int* in_sizes, int n_in,
                              void* d_out, int out_size) {
    const float* nodes = (const float*)d_in[0];
    const float* pe    = (const float*)d_in[1];
    const int*   mask  = (const int*)d_in[2];
    const float* globs = (const float*)d_in[3];
    const float* ln_g  = (const float*)d_in[4];
    const float* ln_b  = (const float*)d_in[5];
    const float* fw1   = (const float*)d_in[6];
    const float* fb1   = (const float*)d_in[7];
    const float* fw2   = (const float*)d_in[8];
    const float* fb2   = (const float*)d_in[9];
    const float* aw1   = (const float*)d_in[10];
    const float* ab1   = (const float*)d_in[11];
    const float* aw2   = (const float*)d_in[12];
    const float* ab2   = (const float*)d_in[13];
    float* out = (float*)d_out;

    float *inp, *h1, *a1, *feats;
    cudaGetSymbolAddress((void**)&inp,   g_inp);
    cudaGetSymbolAddress((void**)&h1,    g_h1);
    cudaGetSymbolAddress((void**)&a1,    g_a1);
    cudaGetSymbolAddress((void**)&feats, g_feats);

    prep_kernel<<<MROWS, 128>>>(nodes, pe, globs, ln_g, ln_b);

    sgemm_kernel<true><<<dim3(FEAT_HID / 128, MROWS / 128), 256>>>(
        inp, fw1, fb1, h1, IN_DIM, FEAT_HID);
    sgemm_kernel<true><<<dim3(ATTN_HID / 128, MROWS / 128), 256>>>(
        inp, aw1, ab1, a1, IN_DIM, ATTN_HID);
    sgemm_kernel<false><<<dim3(FEAT_OUT / 128, MROWS / 128), 256>>>(
        h1, fw2, fb2, feats, FEAT_HID, FEAT_OUT);

    scores_kernel<<<MROWS / 8, 256>>>(a1, aw2, ab2);
    softmax_kernel<<<BATCH, 256>>>(mask);
    finalize_kernel<<<BATCH, 256>>>(nodes, mask, out);
}

// round 3
// speedup vs baseline: 1.6381x; 1.6381x over previous
#include <cuda_runtime.h>
#include <math.h>
#include <stdint.h>

// ---------------- problem constants ----------------
#define BATCH    512
#define NNODE    256
#define MROWS    (BATCH*NNODE)   // 131072
#define NODE_D   256
#define FEAT_IN  512
#define GLOB_D   64
#define IN_DIM   576             // FEAT_IN + GLOB_D
#define FEAT_HID 1024
#define ATTN_HID 256
#define FEAT_OUT 256
#define NHEADS   4
#define LN_EPS   1e-5f

// ---------------- scratch (static device globals; no allocation) ----------------
__device__ float g_inp[(size_t)MROWS * IN_DIM];
__device__ float g_h1[(size_t)MROWS * FEAT_HID];
__device__ float g_a1[(size_t)MROWS * ATTN_HID];
__device__ float g_feats[(size_t)MROWS * FEAT_OUT];
__device__ float g_scores[(size_t)MROWS * NHEADS];
__device__ float g_w[(size_t)MROWS * NHEADS];

// ---------------- stage 1: LayerNorm(concat) + ctx concat ----------------
__global__ void prep_kernel(const float* __restrict__ nodes,
                            const float* __restrict__ pe,
                            const float* __restrict__ globs,
                            const float* __restrict__ ln_g,
                            const float* __restrict__ ln_b) {
    int row = blockIdx.x;
    int t = threadIdx.x;        // 0..127
    int b = row >> 8;

    float4 v;
    if (t < 64) v = ((const float4*)(nodes + (size_t)row * NODE_D))[t];
    else        v = ((const float4*)(pe    + (size_t)row * NODE_D))[t - 64];

    float s  = v.x + v.y + v.z + v.w;
    float ss = v.x * v.x + v.y * v.y + v.z * v.z + v.w * v.w;
    #pragma unroll
    for (int o = 16; o; o >>= 1) {
        s  += __shfl_xor_sync(0xFFFFFFFFu, s, o);
        ss += __shfl_xor_sync(0xFFFFFFFFu, ss, o);
    }
    __shared__ float sh_s[4], sh_ss[4];
    if ((t & 31) == 0) { sh_s[t >> 5] = s; sh_ss[t >> 5] = ss; }
    __syncthreads();
    float mean = (sh_s[0] + sh_s[1] + sh_s[2] + sh_s[3]) * (1.f / 512.f);
    float m2   = (sh_ss[0] + sh_ss[1] + sh_ss[2] + sh_ss[3]) * (1.f / 512.f);
    float rstd = rsqrtf(m2 - mean * mean + LN_EPS);

    float4 g  = ((const float4*)ln_g)[t];
    float4 bt = ((const float4*)ln_b)[t];
    float4 o;
    o.x = (v.x - mean) * rstd * g.x + bt.x;
    o.y = (v.y - mean) * rstd * g.y + bt.y;
    o.z = (v.z - mean) * rstd * g.z + bt.z;
    o.w = (v.w - mean) * rstd * g.w + bt.w;
    ((float4*)(g_inp + (size_t)row * IN_DIM))[t] = o;
    if (t < 16) {
        ((float4*)(g_inp + (size_t)row * IN_DIM + FEAT_IN))[t] =
            ((const float4*)(globs + (size_t)b * GLOB_D))[t];
    }
}

// ---------------- TF32 helpers ----------------
__device__ __forceinline__ uint32_t f2tf(float x) {
    uint32_t r;
    asm("cvt.rna.tf32.f32 %0, %1;" : "=r"(r) : "f"(x));
    return r;
}

__device__ __forceinline__ void mma_tf32(float* c, const uint32_t* a, const uint32_t* b) {
    asm volatile(
        "mma.sync.aligned.m16n8k8.row.col.f32.tf32.tf32.f32 "
        "{%0,%1,%2,%3}, {%4,%5,%6,%7}, {%8,%9}, {%0,%1,%2,%3};"
        : "+f"(c[0]), "+f"(c[1]), "+f"(c[2]), "+f"(c[3])
        : "r"(a[0]), "r"(a[1]), "r"(a[2]), "r"(a[3]), "r"(b[0]), "r"(b[1]));
}

// ---------------- stage 2: TF32 tensor-core GEMM, C = act(A @ W + bias) ----------------
// A:[M,K] row-major fp32, W:[K,Nc] row-major fp32. Tile 128x128, BK=32.
// 8 warps: 2 (m) x 4 (n); warp tile 64x32 = 4x4 m16n8k8 frags.
#define AST 36   // As row stride (floats) -> conflict-free frag reads
#define BST 136  // Bs row stride
template <bool SILU>
__global__ void __launch_bounds__(256)
gemm_tf32_kernel(const float* __restrict__ A, const float* __restrict__ W,
                 const float* __restrict__ bias, float* __restrict__ C,
                 int K, int Nc) {
    __shared__ uint32_t As[128 * AST];
    __shared__ uint32_t Bs[32 * BST];

    int t = threadIdx.x;
    int lane = t & 31, warp = t >> 5;
    int wm = warp >> 2, wn = warp & 3;           // 2 x 4 warp grid
    int qr = lane >> 2, qc = lane & 3;
    int brow = blockIdx.y * 128;
    int bcol = blockIdx.x * 128;

    float acc[4][4][4];
    #pragma unroll
    for (int i = 0; i < 4; i++)
        #pragma unroll
        for (int j = 0; j < 4; j++)
            #pragma unroll
            for (int k = 0; k < 4; k++) acc[i][j][k] = 0.f;

    // global-load mapping
    const float* Aptr = A + (size_t)(brow + (t >> 1)) * K + (t & 1) * 16;
    const float* Wptr = W + (size_t)(t >> 3) * Nc + bcol + (t & 7) * 16;
    uint32_t* AsW = As + (t >> 1) * AST + (t & 1) * 16;
    uint32_t* BsW = Bs + (t >> 3) * BST + (t & 7) * 16;

    float4 av[4], bv[4];
    #pragma unroll
    for (int i = 0; i < 4; i++) {
        av[i] = *(const float4*)(Aptr + i * 4);
        bv[i] = *(const float4*)(Wptr + i * 4);
    }

    int nk = K >> 5;
    for (int kt = 0; kt < nk; kt++) {
        __syncthreads();
        #pragma unroll
        for (int i = 0; i < 4; i++) {
            AsW[i * 4 + 0] = f2tf(av[i].x);
            AsW[i * 4 + 1] = f2tf(av[i].y);
            AsW[i * 4 + 2] = f2tf(av[i].z);
            AsW[i * 4 + 3] = f2tf(av[i].w);
            BsW[i * 4 + 0] = f2tf(bv[i].x);
            BsW[i * 4 + 1] = f2tf(bv[i].y);
            BsW[i * 4 + 2] = f2tf(bv[i].z);
            BsW[i * 4 + 3] = f2tf(bv[i].w);
        }
        __syncthreads();
        if (kt + 1 < nk) {
            int k0 = (kt + 1) * 32;
            #pragma unroll
            for (int i = 0; i < 4; i++) {
                av[i] = *(const float4*)(Aptr + k0 + i * 4);
                bv[i] = *(const float4*)(Wptr + (size_t)k0 * Nc + i * 4);
            }
        }
        #pragma unroll
        for (int ks = 0; ks < 4; ks++) {
            int kc = ks * 8;
            uint32_t a[4][4], b[4][2];
            #pragma unroll
            for (int im = 0; im < 4; im++) {
                int r0 = wm * 64 + im * 16 + qr;
                a[im][0] = As[r0 * AST + kc + qc];
                a[im][1] = As[(r0 + 8) * AST + kc + qc];
                a[im][2] = As[r0 * AST + kc + 4 + qc];
                a[im][3] = As[(r0 + 8) * AST + kc + 4 + qc];
            }
            #pragma unroll
            for (int jn = 0; jn < 4; jn++) {
                int c0 = wn * 32 + jn * 8 + qr;
                b[jn][0] = Bs[(kc + qc) * BST + c0];
                b[jn][1] = Bs[(kc + 4 + qc) * BST + c0];
            }
            #pragma unroll
            for (int im = 0; im < 4; im++)
                #pragma unroll
                for (int jn = 0; jn < 4; jn++)
                    mma_tf32(acc[im][jn], a[im], b[jn]);
        }
    }

    // epilogue: bias + optional SiLU
    #pragma unroll
    for (int im = 0; im < 4; im++) {
        #pragma unroll
        for (int jn = 0; jn < 4; jn++) {
            int row = brow + wm * 64 + im * 16 + qr;
            int col = bcol + wn * 32 + jn * 8 + 2 * qc;
            float b0 = bias[col], b1 = bias[col + 1];
            float v0 = acc[im][jn][0] + b0;
            float v1 = acc[im][jn][1] + b1;
            float v2 = acc[im][jn][2] + b0;
            float v3 = acc[im][jn][3] + b1;
            if (SILU) {
                v0 = v0 / (1.f + __expf(-v0));
                v1 = v1 / (1.f + __expf(-v1));
                v2 = v2 / (1.f + __expf(-v2));
                v3 = v3 / (1.f + __expf(-v3));
            }
            float2 r0 = {v0, v1}, r1 = {v2, v3};
            *(float2*)&C[(size_t)row * Nc + col] = r0;
            *(float2*)&C[(size_t)(row + 8) * Nc + col] = r1;
        }
    }
}

// ---------------- stage 3: scores = A1 @ aw2 + ab2 ----------------
__global__ void scores_kernel(const float* __restrict__ A1,
                              const float* __restrict__ aw2,
                              const float* __restrict__ ab2) {
    int warp = (blockIdx.x * blockDim.x + threadIdx.x) >> 5;
    int lane = threadIdx.x & 31;
    if (warp >= MROWS) return;
    const float* a = A1 + (size_t)warp * ATTN_HID;
    float acc0 = 0.f, acc1 = 0.f, acc2 = 0.f, acc3 = 0.f;
    #pragma unroll
    for (int c = 0; c < 8; c++) {
        int k = c * 32 + lane;
        float av = a[k];
        float4 w = ((const float4*)aw2)[k];
        acc0 += av * w.x; acc1 += av * w.y; acc2 += av * w.z; acc3 += av * w.w;
    }
    #pragma unroll
    for (int o = 16; o; o >>= 1) {
        acc0 += __shfl_xor_sync(0xFFFFFFFFu, acc0, o);
        acc1 += __shfl_xor_sync(0xFFFFFFFFu, acc1, o);
        acc2 += __shfl_xor_sync(0xFFFFFFFFu, acc2, o);
        acc3 += __shfl_xor_sync(0xFFFFFFFFu, acc3, o);
    }
    if (lane == 0) {
        float4 r;
        r.x = acc0 + ab2[0]; r.y = acc1 + ab2[1];
        r.z = acc2 + ab2[2]; r.w = acc3 + ab2[3];
        ((float4*)g_scores)[warp] = r;
    }
}

// ---------------- stage 4: masked softmax over nodes ----------------
__global__ void softmax_kernel(const int* __restrict__ mask) {
    int b = blockIdx.x;
    int t = threadIdx.x;
    int valid = mask[b * NNODE + t];
    __shared__ float sred[8];
    #pragma unroll
    for (int h = 0; h < NHEADS; h++) {
        float s = valid ? g_scores[((size_t)b * NNODE + t) * NHEADS + h] * 0.0625f
                        : -INFINITY;
        float m = s;
        #pragma unroll
        for (int o = 16; o; o >>= 1) m = fmaxf(m, __shfl_xor_sync(0xFFFFFFFFu, m, o));
        if ((t & 31) == 0) sred[t >> 5] = m;
        __syncthreads();
        m = fmaxf(fmaxf(fmaxf(sred[0], sred[1]), fmaxf(sred[2], sred[3])),
                  fmaxf(fmaxf(sred[4], sred[5]), fmaxf(sred[6], sred[7])));
        __syncthreads();
        float e = expf(s - m);
        float sum = e;
        #pragma unroll
        for (int o = 16; o; o >>= 1) sum += __shfl_xor_sync(0xFFFFFFFFu, sum, o);
        if ((t & 31) == 0) sred[t >> 5] = sum;
        __syncthreads();
        sum = sred[0] + sred[1] + sred[2] + sred[3] +
              sred[4] + sred[5] + sred[6] + sred[7];
        g_w[((size_t)b * NNODE + t) * NHEADS + h] = e / sum;
        __syncthreads();
    }
}

// ---------------- stage 5: residual + mask + attention pooling ----------------
__global__ void finalize_kernel(const float* __restrict__ nodes,
                                const int* __restrict__ mask,
                                float* __restrict__ out) {
    int b = blockIdx.x;
    int c = threadIdx.x;
    int h = c >> 6;
    const float* nb = nodes   + (size_t)b * NNODE * FEAT_OUT;
    const float* fb = g_feats + (size_t)b * NNODE * FEAT_OUT;
    float*       ob = out     + (size_t)b * NNODE * FEAT_OUT;
    float acc = 0.f;
    for (int n = 0; n < NNODE; n++) {
        float f = mask[b * NNODE + n] ? fb[n * FEAT_OUT + c] : 0.f;
        float v = nb[n * FEAT_OUT + c] + f;
        ob[n * FEAT_OUT + c] = v;
        acc += v * g_w[((size_t)b * NNODE + n) * NHEADS + h];
    }
    out[(size_t)MROWS * FEAT_OUT + (size_t)b * FEAT_OUT + c] = acc;
}

// ---------------- launch ----------------
extern "C" void kernel_launch(void* const* d_in, const int* in_sizes, int n_in,
                              void* d_out, int out_size) {
    const float* nodes = (const float*)d_in[0];
    const float* pe    = (const float*)d_in[1];
    const int*   mask  = (const int*)d_in[2];
    const float* globs = (const float*)d_in[3];
    const float* ln_g  = (const float*)d_in[4];
    const float* ln_b  = (const float*)d_in[5];
    const float* fw1   = (const float*)d_in[6];
    const float* fb1   = (const float*)d_in[7];
    const float* fw2   = (const float*)d_in[8];
    const float* fb2   = (const float*)d_in[9];
    const float* aw1   = (const float*)d_in[10];
    const float* ab1   = (const float*)d_in[11];
    const float* aw2   = (const float*)d_in[12];
    const float* ab2   = (const float*)d_in[13];
    float* out = (float*)d_out;

    float *inp, *h1, *a1, *feats;
    cudaGetSymbolAddress((void**)&inp,   g_inp);
    cudaGetSymbolAddress((void**)&h1,    g_h1);
    cudaGetSymbolAddress((void**)&a1,    g_a1);
    cudaGetSymbolAddress((void**)&feats, g_feats);

    prep_kernel<<<MROWS, 128>>>(nodes, pe, globs, ln_g, ln_b);

    gemm_tf32_kernel<true><<<dim3(FEAT_HID / 128, MROWS / 128), 256>>>(
        inp, fw1, fb1, h1, IN_DIM, FEAT_HID);
    gemm_tf32_kernel<true><<<dim3(ATTN_HID / 128, MROWS / 128), 256>>>(
        inp, aw1, ab1, a1, IN_DIM, ATTN_HID);
    gemm_tf32_kernel<false><<<dim3(FEAT_OUT / 128, MROWS / 128), 256>>>(
        h1, fw2, fb2, feats, FEAT_HID, FEAT_OUT);

    scores_kernel<<<MROWS / 8, 256>>>(a1, aw2, ab2);
    softmax_kernel<<<BATCH, 256>>>(mask);
    finalize_kernel<<<BATCH, 256>>>(nodes, mask, out);
}

// round 7
// speedup vs baseline: 2.0951x; 1.2790x over previous
#include <cuda_runtime.h>
#include <math.h>
#include <stdint.h>

// ---------------- problem constants ----------------
#define BATCH    512
#define NNODE    256
#define MROWS    (BATCH*NNODE)   // 131072
#define NODE_D   256
#define FEAT_IN  512
#define GLOB_D   64
#define IN_DIM   576             // FEAT_IN + GLOB_D
#define FEAT_HID 1024
#define ATTN_HID 256
#define FEAT_OUT 256
#define NHEADS   4
#define LN_EPS   1e-5f

// ---------------- scratch (static device globals; no allocation) ----------------
__device__ float g_inp[(size_t)MROWS * IN_DIM];
__device__ float g_h1[(size_t)MROWS * FEAT_HID];
__device__ float g_a1[(size_t)MROWS * ATTN_HID];
__device__ float g_feats[(size_t)MROWS * FEAT_OUT];
__device__ float g_scores[(size_t)MROWS * NHEADS];
__device__ float g_w[(size_t)MROWS * NHEADS];
__device__ float g_fw1r[(size_t)IN_DIM * FEAT_HID];
__device__ float g_aw1r[(size_t)IN_DIM * ATTN_HID];
__device__ float g_fw2r[(size_t)FEAT_HID * FEAT_OUT];

// ---------------- TF32 helpers ----------------
__device__ __forceinline__ uint32_t f2tf(float x) {
    uint32_t r;
    asm("cvt.rna.tf32.f32 %0, %1;" : "=r"(r) : "f"(x));
    return r;
}
__device__ __forceinline__ float f2tf_f(float x) { return __uint_as_float(f2tf(x)); }

__device__ __forceinline__ void mma_tf32(float* c, const uint32_t* a, const uint32_t* b) {
    asm volatile(
        "mma.sync.aligned.m16n8k8.row.col.f32.tf32.tf32.f32 "
        "{%0,%1,%2,%3}, {%4,%5,%6,%7}, {%8,%9}, {%0,%1,%2,%3};"
        : "+f"(c[0]), "+f"(c[1]), "+f"(c[2]), "+f"(c[3])
        : "r"(a[0]), "r"(a[1]), "r"(a[2]), "r"(a[3]), "r"(b[0]), "r"(b[1]));
}

// ---------------- cp.async helpers ----------------
__device__ __forceinline__ void cp_async16(uint32_t saddr, const void* g) {
    asm volatile("cp.async.cg.shared.global [%0], [%1], 16;" :: "r"(saddr), "l"(g));
}
__device__ __forceinline__ void cp_commit() {
    asm volatile("cp.async.commit_group;");
}
template <int N>
__device__ __forceinline__ void cp_wait() {
    asm volatile("cp.async.wait_group %0;" :: "n"(N));
}

// ---------------- stage 0: round weights to tf32 (RNA) once per launch ----------------
__global__ void round_kernel(const float* __restrict__ in, float* __restrict__ out, int n) {
    int i = blockIdx.x * blockDim.x + threadIdx.x;
    if (i < n) out[i] = f2tf_f(in[i]);
}

// ---------------- stage 1: LayerNorm(concat) + ctx concat (tf32-rounded output) ----------------
__global__ void prep_kernel(const float* __restrict__ nodes,
                            const float* __restrict__ pe,
                            const float* __restrict__ globs,
                            const float* __restrict__ ln_g,
                            const float* __restrict__ ln_b) {
    int row = blockIdx.x;
    int t = threadIdx.x;        // 0..127
    int b = row >> 8;

    float4 v;
    if (t < 64) v = ((const float4*)(nodes + (size_t)row * NODE_D))[t];
    else        v = ((const float4*)(pe    + (size_t)row * NODE_D))[t - 64];

    float s  = v.x + v.y + v.z + v.w;
    float ss = v.x * v.x + v.y * v.y + v.z * v.z + v.w * v.w;
    #pragma unroll
    for (int o = 16; o; o >>= 1) {
        s  += __shfl_xor_sync(0xFFFFFFFFu, s, o);
        ss += __shfl_xor_sync(0xFFFFFFFFu, ss, o);
    }
    __shared__ float sh_s[4], sh_ss[4];
    if ((t & 31) == 0) { sh_s[t >> 5] = s; sh_ss[t >> 5] = ss; }
    __syncthreads();
    float mean = (sh_s[0] + sh_s[1] + sh_s[2] + sh_s[3]) * (1.f / 512.f);
    float m2   = (sh_ss[0] + sh_ss[1] + sh_ss[2] + sh_ss[3]) * (1.f / 512.f);
    float rstd = rsqrtf(m2 - mean * mean + LN_EPS);

    float4 g  = ((const float4*)ln_g)[t];
    float4 bt = ((const float4*)ln_b)[t];
    float4 o;
    o.x = f2tf_f((v.x - mean) * rstd * g.x + bt.x);
    o.y = f2tf_f((v.y - mean) * rstd * g.y + bt.y);
    o.z = f2tf_f((v.z - mean) * rstd * g.z + bt.z);
    o.w = f2tf_f((v.w - mean) * rstd * g.w + bt.w);
    ((float4*)(g_inp + (size_t)row * IN_DIM))[t] = o;
    if (t < 16) {
        float4 c = ((const float4*)(globs + (size_t)b * GLOB_D))[t];
        c.x = f2tf_f(c.x); c.y = f2tf_f(c.y); c.z = f2tf_f(c.z); c.w = f2tf_f(c.w);
        ((float4*)(g_inp + (size_t)row * IN_DIM + FEAT_IN))[t] = c;
    }
}

// ---------------- stage 2: TF32 tensor-core GEMM with cp.async 2-stage pipeline ----------
// Inputs MUST already be tf32-rounded fp32 bits. Tile 128x128, BK=32.
// 8 warps: 2(m) x 4(n); warp tile 64x32 = 4x4 m16n8k8 frags.
#define AST 36   // As row stride (floats), 144B, conflict-free + 16B-aligned
#define BST 136  // Bs row stride (floats), 544B
#define A_STAGE (128 * AST)
#define B_STAGE (32 * BST)
#define SMEM_FLOATS (2 * (A_STAGE + B_STAGE))
#define SMEM_BYTES (SMEM_FLOATS * 4)

template <bool SILU, bool ROUND_OUT>
__global__ void __launch_bounds__(256, 2)
gemm_tf32_cp(const float* __restrict__ A, const float* __restrict__ W,
             const float* __restrict__ bias, float* __restrict__ C,
             int K, int Nc) {
    extern __shared__ float sm[];
    float* As = sm;                     // [2][128*AST]
    float* Bs = sm + 2 * A_STAGE;       // [2][32*BST]

    int t = threadIdx.x;
    int lane = t & 31, warp = t >> 5;
    int wm = warp >> 2, wn = warp & 3;
    int qr = lane >> 2, qc = lane & 3;
    int brow = blockIdx.y * 128;
    int bcol = blockIdx.x * 128;

    float acc[4][4][4];
    #pragma unroll
    for (int i = 0; i < 4; i++)
        #pragma unroll
        for (int j = 0; j < 4; j++)
            #pragma unroll
            for (int k = 0; k < 4; k++) acc[i][j][k] = 0.f;

    // cp.async mappings: A: thread -> row t>>1, 16 floats at (t&1)*16
    //                    B: thread -> k-row t>>3, 16 floats at (t&7)*16
    int arow = t >> 1, acol = (t & 1) * 16;
    int bkrow = t >> 3, bcol16 = (t & 7) * 16;
    const float* Ag = A + (size_t)(brow + arow) * K + acol;
    const float* Wg = W + (size_t)bkrow * Nc + bcol + bcol16;
    uint32_t AsBase = (uint32_t)__cvta_generic_to_shared(As) + (arow * AST + acol) * 4;
    uint32_t BsBase = (uint32_t)__cvta_generic_to_shared(Bs) + (bkrow * BST + bcol16) * 4;

    int nk = K >> 5;

    // prologue: issue stages 0 and 1
    #pragma unroll
    for (int s = 0; s < 2; s++) {
        int k0 = s * 32;
        uint32_t as = AsBase + s * A_STAGE * 4;
        uint32_t bs = BsBase + s * B_STAGE * 4;
        #pragma unroll
        for (int j = 0; j < 4; j++) {
            cp_async16(as + j * 16, Ag + k0 + j * 4);
            cp_async16(bs + j * 16, Wg + (size_t)k0 * Nc + j * 4);
        }
        cp_commit();
    }

    for (int kt = 0; kt < nk; kt++) {
        int buf = kt & 1;
        if (kt + 1 < nk) cp_wait<1>(); else cp_wait<0>();
        __syncthreads();

        const uint32_t* Ab = (const uint32_t*)(As + buf * A_STAGE);
        const uint32_t* Bb = (const uint32_t*)(Bs + buf * B_STAGE);
        #pragma unroll
        for (int ks = 0; ks < 4; ks++) {
            int kc = ks * 8;
            uint32_t a[4][4], b[4][2];
            #pragma unroll
            for (int im = 0; im < 4; im++) {
                int r0 = wm * 64 + im * 16 + qr;
                a[im][0] = Ab[r0 * AST + kc + qc];
                a[im][1] = Ab[(r0 + 8) * AST + kc + qc];
                a[im][2] = Ab[r0 * AST + kc + 4 + qc];
                a[im][3] = Ab[(r0 + 8) * AST + kc + 4 + qc];
            }
            #pragma unroll
            for (int jn = 0; jn < 4; jn++) {
                int c0 = wn * 32 + jn * 8 + qr;
                b[jn][0] = Bb[(kc + qc) * BST + c0];
                b[jn][1] = Bb[(kc + 4 + qc) * BST + c0];
            }
            #pragma unroll
            for (int im = 0; im < 4; im++)
                #pragma unroll
                for (int jn = 0; jn < 4; jn++)
                    mma_tf32(acc[im][jn], a[im], b[jn]);
        }
        __syncthreads();

        if (kt + 2 < nk) {
            int k0 = (kt + 2) * 32;
            uint32_t as = AsBase + buf * A_STAGE * 4;
            uint32_t bs = BsBase + buf * B_STAGE * 4;
            #pragma unroll
            for (int j = 0; j < 4; j++) {
                cp_async16(as + j * 16, Ag + k0 + j * 4);
                cp_async16(bs + j * 16, Wg + (size_t)k0 * Nc + j * 4);
            }
            cp_commit();
        }
    }

    // epilogue: bias + optional SiLU (+ optional tf32 re-round for chained GEMM input)
    #pragma unroll
    for (int im = 0; im < 4; im++) {
        #pragma unroll
        for (int jn = 0; jn < 4; jn++) {
            int row = brow + wm * 64 + im * 16 + qr;
            int col = bcol + wn * 32 + jn * 8 + 2 * qc;
            float b0 = bias[col], b1 = bias[col + 1];
            float v0 = acc[im][jn][0] + b0;
            float v1 = acc[im][jn][1] + b1;
            float v2 = acc[im][jn][2] + b0;
            float v3 = acc[im][jn][3] + b1;
            if (SILU) {
                v0 = v0 / (1.f + __expf(-v0));
                v1 = v1 / (1.f + __expf(-v1));
                v2 = v2 / (1.f + __expf(-v2));
                v3 = v3 / (1.f + __expf(-v3));
            }
            if (ROUND_OUT) {
                v0 = f2tf_f(v0); v1 = f2tf_f(v1);
                v2 = f2tf_f(v2); v3 = f2tf_f(v3);
            }
            float2 r0 = {v0, v1}, r1 = {v2, v3};
            *(float2*)&C[(size_t)row * Nc + col] = r0;
            *(float2*)&C[(size_t)(row + 8) * Nc + col] = r1;
        }
    }
}

// ---------------- stage 3: scores = A1 @ aw2 + ab2 ----------------
__global__ void scores_kernel(const float* __restrict__ A1,
                              const float* __restrict__ aw2,
                              const float* __restrict__ ab2) {
    int warp = (blockIdx.x * blockDim.x + threadIdx.x) >> 5;
    int lane = threadIdx.x & 31;
    if (warp >= MROWS) return;
    const float* a = A1 + (size_t)warp * ATTN_HID;
    float acc0 = 0.f, acc1 = 0.f, acc2 = 0.f, acc3 = 0.f;
    #pragma unroll
    for (int c = 0; c < 8; c++) {
        int k = c * 32 + lane;
        float av = a[k];
        float4 w = ((const float4*)aw2)[k];
        acc0 += av * w.x; acc1 += av * w.y; acc2 += av * w.z; acc3 += av * w.w;
    }
    #pragma unroll
    for (int o = 16; o; o >>= 1) {
        acc0 += __shfl_xor_sync(0xFFFFFFFFu, acc0, o);
        acc1 += __shfl_xor_sync(0xFFFFFFFFu, acc1, o);
        acc2 += __shfl_xor_sync(0xFFFFFFFFu, acc2, o);
        acc3 += __shfl_xor_sync(0xFFFFFFFFu, acc3, o);
    }
    if (lane == 0) {
        float4 r;
        r.x = acc0 + ab2[0]; r.y = acc1 + ab2[1];
        r.z = acc2 + ab2[2]; r.w = acc3 + ab2[3];
        ((float4*)g_scores)[warp] = r;
    }
}

// ---------------- stage 4: masked softmax over nodes ----------------
__global__ void softmax_kernel(const int* __restrict__ mask) {
    int b = blockIdx.x;
    int t = threadIdx.x;
    int valid = mask[b * NNODE + t];
    __shared__ float sred[8];
    #pragma unroll
    for (int h = 0; h < NHEADS; h++) {
        float s = valid ? g_scores[((size_t)b * NNODE + t) * NHEADS + h] * 0.0625f
                        : -INFINITY;
        float m = s;
        #pragma unroll
        for (int o = 16; o; o >>= 1) m = fmaxf(m, __shfl_xor_sync(0xFFFFFFFFu, m, o));
        if ((t & 31) == 0) sred[t >> 5] = m;
        __syncthreads();
        m = fmaxf(fmaxf(fmaxf(sred[0], sred[1]), fmaxf(sred[2], sred[3])),
                  fmaxf(fmaxf(sred[4], sred[5]), fmaxf(sred[6], sred[7])));
        __syncthreads();
        float e = expf(s - m);
        float sum = e;
        #pragma unroll
        for (int o = 16; o; o >>= 1) sum += __shfl_xor_sync(0xFFFFFFFFu, sum, o);
        if ((t & 31) == 0) sred[t >> 5] = sum;
        __syncthreads();
        sum = sred[0] + sred[1] + sred[2] + sred[3] +
              sred[4] + sred[5] + sred[6] + sred[7];
        g_w[((size_t)b * NNODE + t) * NHEADS + h] = e / sum;
        __syncthreads();
    }
}

// ---------------- stage 5: residual + mask + attention pooling ----------------
__global__ void finalize_kernel(const float* __restrict__ nodes,
                                const int* __restrict__ mask,
                                float* __restrict__ out) {
    int b = blockIdx.x;
    int c = threadIdx.x;
    int h = c >> 6;
    const float* nb = nodes   + (size_t)b * NNODE * FEAT_OUT;
    const float* fb = g_feats + (size_t)b * NNODE * FEAT_OUT;
    float*       ob = out     + (size_t)b * NNODE * FEAT_OUT;
    float acc = 0.f;
    for (int n = 0; n < NNODE; n++) {
        float f = mask[b * NNODE + n] ? fb[n * FEAT_OUT + c] : 0.f;
        float v = nb[n * FEAT_OUT + c] + f;
        ob[n * FEAT_OUT + c] = v;
        acc += v * g_w[((size_t)b * NNODE + n) * NHEADS + h];
    }
    out[(size_t)MROWS * FEAT_OUT + (size_t)b * FEAT_OUT + c] = acc;
}

// ---------------- launch ----------------
extern "C" void kernel_launch(void* const* d_in, const int* in_sizes, int n_in,
                              void* d_out, int out_size) {
    const float* nodes = (const float*)d_in[0];
    const float* pe    = (const float*)d_in[1];
    const int*   mask  = (const int*)d_in[2];
    const float* globs = (const float*)d_in[3];
    const float* ln_g  = (const float*)d_in[4];
    const float* ln_b  = (const float*)d_in[5];
    const float* fw1   = (const float*)d_in[6];
    const float* fb1   = (const float*)d_in[7];
    const float* fw2   = (const float*)d_in[8];
    const float* fb2   = (const float*)d_in[9];
    const float* aw1   = (const float*)d_in[10];
    const float* ab1   = (const float*)d_in[11];
    const float* aw2   = (const float*)d_in[12];
    const float* ab2   = (const float*)d_in[13];
    float* out = (float*)d_out;

    float *inp, *h1, *a1, *feats, *fw1r, *aw1r, *fw2r;
    cudaGetSymbolAddress((void**)&inp,   g_inp);
    cudaGetSymbolAddress((void**)&h1,    g_h1);
    cudaGetSymbolAddress((void**)&a1,    g_a1);
    cudaGetSymbolAddress((void**)&feats, g_feats);
    cudaGetSymbolAddress((void**)&fw1r,  g_fw1r);
    cudaGetSymbolAddress((void**)&aw1r,  g_aw1r);
    cudaGetSymbolAddress((void**)&fw2r,  g_fw2r);

    cudaFuncSetAttribute(gemm_tf32_cp<true, true>,
                         cudaFuncAttributeMaxDynamicSharedMemorySize, SMEM_BYTES);
    cudaFuncSetAttribute(gemm_tf32_cp<true, false>,
                         cudaFuncAttributeMaxDynamicSharedMemorySize, SMEM_BYTES);
    cudaFuncSetAttribute(gemm_tf32_cp<false, false>,
                         cudaFuncAttributeMaxDynamicSharedMemorySize, SMEM_BYTES);

    // round weights to tf32 once per call (cheap, deterministic)
    round_kernel<<<(IN_DIM * FEAT_HID + 255) / 256, 256>>>(fw1, fw1r, IN_DIM * FEAT_HID);
    round_kernel<<<(IN_DIM * ATTN_HID + 255) / 256, 256>>>(aw1, aw1r, IN_DIM * ATTN_HID);
    round_kernel<<<(FEAT_HID * FEAT_OUT + 255) / 256, 256>>>(fw2, fw2r, FEAT_HID * FEAT_OUT);

    prep_kernel<<<MROWS, 128>>>(nodes, pe, globs, ln_g, ln_b);

    gemm_tf32_cp<true, true><<<dim3(FEAT_HID / 128, MROWS / 128), 256, SMEM_BYTES>>>(
        inp, fw1r, fb1, h1, IN_DIM, FEAT_HID);
    gemm_tf32_cp<true, false><<<dim3(ATTN_HID / 128, MROWS / 128), 256, SMEM_BYTES>>>(
        inp, aw1r, ab1, a1, IN_DIM, ATTN_HID);
    gemm_tf32_cp<false, false><<<dim3(FEAT_OUT / 128, MROWS / 128), 256, SMEM_BYTES>>>(
        h1, fw2r, fb2, feats, FEAT_HID, FEAT_OUT);

    scores_kernel<<<MROWS / 8, 256>>>(a1, aw2, ab2);
    softmax_kernel<<<BATCH, 256>>>(mask);
    finalize_kernel<<<BATCH, 256>>>(nodes, mask, out);
}